// round 3
// baseline (speedup 1.0000x reference)
#include <cuda_runtime.h>
#include <math.h>

#define VV   200000
#define BQ   2048
#define FF   5
#define NNB  64
#define KSEL 32
#define DD   256
#define DMV  512     // DM = 2*D
#define HID  1024    // 2*DM
#define NG   2048    // packed gate cols: i,f,g,o each [:512]
#define KDIM 512
#define MROWS (2*(BQ+FF))   // 4106 neighbor-encoder rows
#define MPAD  4224

// ---------------- static scratch ----------------
__device__ float g_meancat[MPAD*2*DD];      // 4224 x 512
__device__ float g_nb[MPAD*DD];             // 4224 x 256 (qn = rows 0..4095, sn = 4096..4105)
__device__ float g_supp_enc[FF*DMV];
__device__ float g_sg[DMV];
__device__ float g_sgn[DMV];
__device__ float g_sgr[NG];
__device__ float g_biasp[NG];
__device__ float g_qg[BQ*DMV];
__device__ float g_Gbase[(size_t)BQ*NG];
__device__ float g_gates[(size_t)BQ*NG];
__device__ float g_c[BQ*DMV];
__device__ float g_h[BQ*DMV];

// ---------------- helpers ----------------
__device__ __forceinline__ float warp_reduce_sum(float v) {
#pragma unroll
    for (int o = 16; o > 0; o >>= 1) v += __shfl_down_sync(0xffffffffu, v, o);
    return v;
}
__device__ __forceinline__ float sigmoidf_(float x) { return 1.0f / (1.0f + expf(-x)); }
__device__ __forceinline__ int clamp_id(int id) { return (id < 0 || id > VV) ? VV : id; }

__device__ __forceinline__ float block_reduce_256(float v, float* red) {
    int lane = threadIdx.x & 31, w = threadIdx.x >> 5;
    v = warp_reduce_sum(v);
    if (lane == 0) red[w] = v;
    __syncthreads();
    if (threadIdx.x == 0) {
        float s = 0.f;
#pragma unroll
        for (int i = 0; i < 8; i++) s += red[i];
        red[0] = s;
    }
    __syncthreads();
    float s = red[0];
    __syncthreads();
    return s;
}

// ---------------- neighbor encoder: top-K select + mean of (rel,ent) ----------------
// grid (BQ+FF, 2), 256 threads. Writes meancat row r = row*2+side (query) / 4096+f*2+side.
__global__ __launch_bounds__(256) void nbenc_kernel(
    const int* __restrict__ query, const int* __restrict__ support,
    const int* __restrict__ qlc, const int* __restrict__ qrc,
    const int* __restrict__ slc, const int* __restrict__ srrc,
    const float* __restrict__ emb, float* __restrict__ meancat_out)
{
    int row = blockIdx.x, side = blockIdx.y;
    const int* conn; int id; int r;
    if (row < BQ) {
        conn = (side == 0 ? qlc : qrc) + row * NNB * 2;
        id   = query[row * 2 + side];
        r    = row * 2 + side;
    } else {
        int f = row - BQ;
        conn = (side == 0 ? slc : srrc) + f * NNB * 2;
        id   = support[f * 2 + side];
        r    = 2 * BQ + f * 2 + side;
    }
    id = clamp_id(id);
    int t = threadIdx.x, lane = t & 31, warp = t >> 5;

    __shared__ float csm[DD];
    __shared__ float sims[NNB];
    __shared__ int   sel[NNB];
    __shared__ float red[8];
    __shared__ float cn_s;

    float cv = emb[(size_t)id * DD + t];
    csm[t] = cv;
    float cs = block_reduce_256(cv * cv, red);
    if (t == 0) cn_s = sqrtf(cs);
    __syncthreads();

#pragma unroll
    for (int i = 0; i < 8; i++) {
        int n = warp * 8 + i;
        int eid = clamp_id(conn[n * 2 + 1]);
        const float* er = emb + (size_t)eid * DD;
        float dot = 0.f, nn2 = 0.f;
#pragma unroll
        for (int d = lane; d < DD; d += 32) {
            float e = er[d];
            dot += e * csm[d];
            nn2 += e * e;
        }
        dot = warp_reduce_sum(dot);
        nn2 = warp_reduce_sum(nn2);
        if (lane == 0) sims[n] = dot / fmaxf(cn_s * sqrtf(nn2), 1e-8f);
    }
    __syncthreads();

    // stable top-K membership (ties -> lower index)
    if (t < NNB) {
        float s = sims[t];
        int cnt = 0;
#pragma unroll
        for (int m = 0; m < NNB; m++) {
            float sm = sims[m];
            cnt += (sm > s) || (sm == s && m < t);
        }
        sel[t] = (cnt < KSEL);
    }
    __syncthreads();

    float accR = 0.f, accE = 0.f;
    for (int n = 0; n < NNB; n++) {
        if (!sel[n]) continue;
        int rid = clamp_id(conn[n * 2 + 0]);
        int eid = clamp_id(conn[n * 2 + 1]);
        accR += emb[(size_t)rid * DD + t];
        accE += emb[(size_t)eid * DD + t];
    }
    float* mc = meancat_out + (size_t)r * (2 * DD);
    mc[t]      = accR * (1.0f / KSEL);   // rel part (cols 0..255)
    mc[DD + t] = accE * (1.0f / KSEL);   // ent part (cols 256..511)
}

// ---------------- GCN projection: nb = tanh(meancat @ gcnw^T + wb + b) ----------------
// M=4106 (guarded), N=256, K=512. 128x128 tiles, 256 thr, 8x8/thread.
__global__ __launch_bounds__(256, 2) void gemm_gcn(
    const float* __restrict__ A, const float* __restrict__ W,
    const float* __restrict__ wb, const float* __restrict__ bb,
    float* __restrict__ C, int Mtot)
{
    __shared__ float As[16][132];
    __shared__ float Bs[16][132];
    const int t = threadIdx.x;
    const int tx = t & 15, ty = t >> 4;
    const int m0 = blockIdx.y * 128, n0 = blockIdx.x * 128;

    float acc[8][8];
#pragma unroll
    for (int i = 0; i < 8; i++)
#pragma unroll
        for (int j = 0; j < 8; j++) acc[i][j] = 0.f;

    for (int k0 = 0; k0 < KDIM; k0 += 16) {
#pragma unroll
        for (int rr = 0; rr < 2; ++rr) {
            int idx = t + rr * 256;
            int row = idx >> 2, kk = (idx & 3) << 2;
            float4 v = *(const float4*)(A + (size_t)(m0 + row) * KDIM + k0 + kk);
            As[kk+0][row] = v.x; As[kk+1][row] = v.y; As[kk+2][row] = v.z; As[kk+3][row] = v.w;
            float4 w = *(const float4*)(W + (size_t)(n0 + row) * KDIM + k0 + kk);
            Bs[kk+0][row] = w.x; Bs[kk+1][row] = w.y; Bs[kk+2][row] = w.z; Bs[kk+3][row] = w.w;
        }
        __syncthreads();
#pragma unroll
        for (int k = 0; k < 16; k++) {
            float4 a0 = *(const float4*)&As[k][ty * 8];
            float4 a1 = *(const float4*)&As[k][ty * 8 + 4];
            float4 b0 = *(const float4*)&Bs[k][tx * 8];
            float4 b1 = *(const float4*)&Bs[k][tx * 8 + 4];
            float av[8] = {a0.x,a0.y,a0.z,a0.w,a1.x,a1.y,a1.z,a1.w};
            float bv[8] = {b0.x,b0.y,b0.z,b0.w,b1.x,b1.y,b1.z,b1.w};
#pragma unroll
            for (int i = 0; i < 8; i++)
#pragma unroll
                for (int j = 0; j < 8; j++) acc[i][j] += av[i] * bv[j];
        }
        __syncthreads();
    }

    float badd[8];
#pragma unroll
    for (int j = 0; j < 8; j++) {
        int n = n0 + tx * 8 + j;
        badd[j] = wb[n] + bb[n];
    }
#pragma unroll
    for (int i = 0; i < 8; i++) {
        int m = m0 + ty * 8 + i;
        if (m >= Mtot) break;
        float* crow = C + (size_t)m * DD + n0 + tx * 8;
#pragma unroll
        for (int j = 0; j < 8; j++) crow[j] = tanhf(acc[i][j] + badd[j]);
    }
}

// ---------------- encoder (MLP + residual + LN) ----------------
__global__ __launch_bounds__(256) void encoder_kernel(
    const float* __restrict__ X, float* __restrict__ Y,
    const float* __restrict__ p1w, const float* __restrict__ p1b,
    const float* __restrict__ p2w, const float* __restrict__ p2b,
    const float* __restrict__ lng, const float* __restrict__ lnb)
{
    int row = blockIdx.x, t = threadIdx.x;
    __shared__ float xs[DMV];
    __shared__ float hs[2 * DMV];
    __shared__ float os[DMV];
    __shared__ float red[8];

    xs[t]       = X[(size_t)row * DMV + t];
    xs[t + 256] = X[(size_t)row * DMV + t + 256];
    __syncthreads();

    {
        float a0 = p1b[t], a1 = p1b[t+256], a2 = p1b[t+512], a3 = p1b[t+768];
        const float4* w0 = (const float4*)(p1w + (size_t)(t)       * KDIM);
        const float4* w1 = (const float4*)(p1w + (size_t)(t + 256) * KDIM);
        const float4* w2 = (const float4*)(p1w + (size_t)(t + 512) * KDIM);
        const float4* w3 = (const float4*)(p1w + (size_t)(t + 768) * KDIM);
        const float4* x4 = (const float4*)xs;
#pragma unroll 4
        for (int k = 0; k < KDIM / 4; k++) {
            float4 xv = x4[k];
            float4 v;
            v = w0[k]; a0 += v.x*xv.x + v.y*xv.y + v.z*xv.z + v.w*xv.w;
            v = w1[k]; a1 += v.x*xv.x + v.y*xv.y + v.z*xv.z + v.w*xv.w;
            v = w2[k]; a2 += v.x*xv.x + v.y*xv.y + v.z*xv.z + v.w*xv.w;
            v = w3[k]; a3 += v.x*xv.x + v.y*xv.y + v.z*xv.z + v.w*xv.w;
        }
        hs[t]       = fmaxf(a0, 0.f);
        hs[t + 256] = fmaxf(a1, 0.f);
        hs[t + 512] = fmaxf(a2, 0.f);
        hs[t + 768] = fmaxf(a3, 0.f);
    }
    __syncthreads();

    {
        float a0 = p2b[t], a1 = p2b[t + 256];
        const float4* w0 = (const float4*)(p2w + (size_t)(t)       * (2 * DMV));
        const float4* w1 = (const float4*)(p2w + (size_t)(t + 256) * (2 * DMV));
        const float4* h4 = (const float4*)hs;
#pragma unroll 4
        for (int k = 0; k < (2 * DMV) / 4; k++) {
            float4 hv = h4[k];
            float4 v;
            v = w0[k]; a0 += v.x*hv.x + v.y*hv.y + v.z*hv.z + v.w*hv.w;
            v = w1[k]; a1 += v.x*hv.x + v.y*hv.y + v.z*hv.z + v.w*hv.w;
        }
        os[t]       = a0 + xs[t];
        os[t + 256] = a1 + xs[t + 256];
    }
    __syncthreads();

    float o0 = os[t], o1 = os[t + 256];
    float msum = block_reduce_256(o0 + o1, red);
    float m = msum * (1.0f / DMV);
    float d0 = o0 - m, d1 = o1 - m;
    float vsum = block_reduce_256(d0 * d0 + d1 * d1, red);
    float rstd = rsqrtf(vsum * (1.0f / DMV) + 1e-5f);
    Y[(size_t)row * DMV + t]       = d0 * rstd * lng[t]       + lnb[t];
    Y[(size_t)row * DMV + t + 256] = d1 * rstd * lng[t + 256] + lnb[t + 256];
}

// ---------------- mean over F support rows + normalized copy ----------------
__global__ void avgnorm_kernel(float* __restrict__ sg, float* __restrict__ sgn,
                               const float* __restrict__ senc)
{
    int t = threadIdx.x; // 512 threads
    __shared__ float red[16];
    float s = 0.f;
#pragma unroll
    for (int f = 0; f < FF; f++) s += senc[f * DMV + t];
    s *= (1.0f / FF);
    sg[t] = s;
    int lane = t & 31, w = t >> 5;
    float v = warp_reduce_sum(s * s);
    if (lane == 0) red[w] = v;
    __syncthreads();
    if (t == 0) {
        float tot = 0.f;
#pragma unroll
        for (int i = 0; i < 16; i++) tot += red[i];
        red[0] = sqrtf(tot);
    }
    __syncthreads();
    float nrm = red[0];
    sgn[t] = s / fmaxf(nrm, 1e-12f);
}

// ---------------- packed constants: sgr[n], biasp[n] ----------------
// packed n -> full gate col jf = (n>>9)*1024 + (n&511)
__global__ __launch_bounds__(256) void pack_kernel(
    float* __restrict__ sgr, float* __restrict__ biasp,
    const float* __restrict__ whh, const float* __restrict__ sg,
    const float* __restrict__ bih, const float* __restrict__ bhh)
{
    int n = (blockIdx.x * blockDim.x + threadIdx.x) >> 5;
    int lane = threadIdx.x & 31;
    if (n >= NG) return;
    int jf = (n >> 9) * HID + (n & 511);
    const float* wr = whh + (size_t)jf * HID + DMV;   // cols 512..1023
    float a = 0.f;
#pragma unroll
    for (int k = lane; k < DMV; k += 32) a += wr[k] * sg[k];
    a = warp_reduce_sum(a);
    if (lane == 0) {
        sgr[n] = a;
        biasp[n] = bih[jf] + bhh[jf];
    }
}

// ---------------- LSTM GEMM: C = A(2048x512) @ Wsel^T + epilogue ----------------
// N-tile n0 maps to W row block (n0>>9)*1024 + (n0&511) (contiguous within tile).
__global__ __launch_bounds__(256, 2) void gemm_epi(
    const float* __restrict__ A,
    const float* __restrict__ W, int ldw,
    float* __restrict__ C,
    const float* __restrict__ addmat,
    const float* __restrict__ addv)
{
    __shared__ float As[16][132];
    __shared__ float Bs[16][132];
    const int t = threadIdx.x;
    const int tx = t & 15, ty = t >> 4;
    const int m0 = blockIdx.y * 128, n0 = blockIdx.x * 128;
    const int wrow0 = (n0 >> 9) * HID + (n0 & 511);

    float acc[8][8];
#pragma unroll
    for (int i = 0; i < 8; i++)
#pragma unroll
        for (int j = 0; j < 8; j++) acc[i][j] = 0.f;

    for (int k0 = 0; k0 < KDIM; k0 += 16) {
#pragma unroll
        for (int rr = 0; rr < 2; ++rr) {
            int idx = t + rr * 256;
            int row = idx >> 2, kk = (idx & 3) << 2;
            float4 v = *(const float4*)(A + (size_t)(m0 + row) * KDIM + k0 + kk);
            As[kk+0][row] = v.x; As[kk+1][row] = v.y; As[kk+2][row] = v.z; As[kk+3][row] = v.w;
            float4 w = *(const float4*)(W + (size_t)(wrow0 + row) * ldw + k0 + kk);
            Bs[kk+0][row] = w.x; Bs[kk+1][row] = w.y; Bs[kk+2][row] = w.z; Bs[kk+3][row] = w.w;
        }
        __syncthreads();
#pragma unroll
        for (int k = 0; k < 16; k++) {
            float4 a0 = *(const float4*)&As[k][ty * 8];
            float4 a1 = *(const float4*)&As[k][ty * 8 + 4];
            float4 b0 = *(const float4*)&Bs[k][tx * 8];
            float4 b1 = *(const float4*)&Bs[k][tx * 8 + 4];
            float av[8] = {a0.x,a0.y,a0.z,a0.w,a1.x,a1.y,a1.z,a1.w};
            float bv[8] = {b0.x,b0.y,b0.z,b0.w,b1.x,b1.y,b1.z,b1.w};
#pragma unroll
            for (int i = 0; i < 8; i++)
#pragma unroll
                for (int j = 0; j < 8; j++) acc[i][j] += av[i] * bv[j];
        }
        __syncthreads();
    }

    float vcol[8];
#pragma unroll
    for (int j = 0; j < 8; j++) vcol[j] = addv ? addv[n0 + tx * 8 + j] : 0.f;

#pragma unroll
    for (int i = 0; i < 8; i++) {
        size_t off = (size_t)(m0 + ty * 8 + i) * NG + n0 + tx * 8;
        float* crow = C + off;
        if (addmat) {
            const float* mrow = addmat + off;
#pragma unroll
            for (int j = 0; j < 8; j++) crow[j] = acc[i][j] + vcol[j] + mrow[j];
        } else {
#pragma unroll
            for (int j = 0; j < 8; j++) crow[j] = acc[i][j] + vcol[j];
        }
    }
}

// ---------------- LSTM elementwise step: updates c, writes h = qg + sig(o)*tanh(c) ----------------
__global__ __launch_bounds__(256) void lstm_step_kernel(
    const float* __restrict__ G, const float* __restrict__ qg,
    float* __restrict__ c, float* __restrict__ h, int first)
{
    int idx = blockIdx.x * blockDim.x + threadIdx.x;   // 0 .. BQ*512-1
    int b = idx >> 9, j = idx & 511;
    const float* g = G + (size_t)b * NG;
    float gi = g[j], gf = g[512 + j], gg = g[1024 + j], go = g[1536 + j];
    float cn = sigmoidf_(gi) * tanhf(gg);
    if (!first) cn += sigmoidf_(gf) * c[idx];
    c[idx] = cn;
    h[idx] = qg[idx] + sigmoidf_(go) * tanhf(cn);
}

// ---------------- final cosine output ----------------
__global__ __launch_bounds__(256) void final_kernel(
    float* __restrict__ out, const float* __restrict__ h,
    const float* __restrict__ sgn)
{
    int b = (blockIdx.x * blockDim.x + threadIdx.x) >> 5;
    int lane = threadIdx.x & 31;
    if (b >= BQ) return;
    float nn = 0.f, dd = 0.f;
#pragma unroll
    for (int d = lane; d < DMV; d += 32) {
        float hv = h[(size_t)b * DMV + d];
        nn += hv * hv;
        dd += hv * sgn[d];
    }
    nn = warp_reduce_sum(nn);
    dd = warp_reduce_sum(dd);
    if (lane == 0) out[b] = dd / fmaxf(sqrtf(nn), 1e-12f);
}

// ---------------- input binding ----------------
enum {
    R_query=0, R_support, R_qlc, R_qld, R_qrc, R_qrd, R_slc, R_sld, R_src, R_srd,
    R_emb, R_gcnw, R_gcnwb, R_gcnb, R_p1w, R_p1b, R_p2w, R_p2b, R_lng, R_lnb,
    R_wih, R_whh, R_bih, R_bhh, R_COUNT
};
static const int DICT_SIZES[R_COUNT] = {
    4096, 10, 262144, 2048, 262144, 2048, 640, 5, 640, 5,
    51200256, 131072, 256, 256, 524288, 1024, 524288, 512, 512, 512,
    2097152, 4194304, 4096, 4096
};
static bool sizes_match(const int* s, const int* exp, int n) {
    for (int i = 0; i < n; i++) if (s[i] != exp[i]) return false;
    return true;
}

// ---------------- launcher ----------------
extern "C" void kernel_launch(void* const* d_in, const int* in_sizes, int n_in,
                              void* d_out, int out_size)
{
    int map[R_COUNT];
    if (n_in >= R_COUNT && sizes_match(in_sizes, DICT_SIZES, R_COUNT)) {
        for (int r = 0; r < R_COUNT; r++) map[r] = r;
    } else {
        bool used[64] = {false};
        for (int r = 0; r < R_COUNT; r++) {
            map[r] = 0;
            for (int i = 0; i < n_in && i < 64; i++) {
                if (!used[i] && in_sizes[i] == DICT_SIZES[r]) { map[r] = i; used[i] = true; break; }
            }
        }
    }

    const int*   query   = (const int*)d_in[map[R_query]];
    const int*   support = (const int*)d_in[map[R_support]];
    const int*   qlc     = (const int*)d_in[map[R_qlc]];
    const int*   qrc     = (const int*)d_in[map[R_qrc]];
    const int*   slc     = (const int*)d_in[map[R_slc]];
    const int*   srrc    = (const int*)d_in[map[R_src]];
    const float* emb     = (const float*)d_in[map[R_emb]];
    const float* gcnw    = (const float*)d_in[map[R_gcnw]];
    const float* gcnwb   = (const float*)d_in[map[R_gcnwb]];
    const float* gcnb    = (const float*)d_in[map[R_gcnb]];
    const float* p1w     = (const float*)d_in[map[R_p1w]];
    const float* p1b     = (const float*)d_in[map[R_p1b]];
    const float* p2w     = (const float*)d_in[map[R_p2w]];
    const float* p2b     = (const float*)d_in[map[R_p2b]];
    const float* lng     = (const float*)d_in[map[R_lng]];
    const float* lnb     = (const float*)d_in[map[R_lnb]];
    const float* wih     = (const float*)d_in[map[R_wih]];
    const float* whh     = (const float*)d_in[map[R_whh]];
    const float* bih     = (const float*)d_in[map[R_bih]];
    const float* bhh     = (const float*)d_in[map[R_bhh]];
    float* out = (float*)d_out;

    float *mc, *nb, *senc, *sg, *sgn, *sgr, *biasp, *qg, *Gbase, *gates, *c, *h;
    cudaGetSymbolAddress((void**)&mc,    g_meancat);
    cudaGetSymbolAddress((void**)&nb,    g_nb);
    cudaGetSymbolAddress((void**)&senc,  g_supp_enc);
    cudaGetSymbolAddress((void**)&sg,    g_sg);
    cudaGetSymbolAddress((void**)&sgn,   g_sgn);
    cudaGetSymbolAddress((void**)&sgr,   g_sgr);
    cudaGetSymbolAddress((void**)&biasp, g_biasp);
    cudaGetSymbolAddress((void**)&qg,    g_qg);
    cudaGetSymbolAddress((void**)&Gbase, g_Gbase);
    cudaGetSymbolAddress((void**)&gates, g_gates);
    cudaGetSymbolAddress((void**)&c,     g_c);
    cudaGetSymbolAddress((void**)&h,     g_h);

    // 1) neighbor top-K means -> meancat (4106 x 512)
    nbenc_kernel<<<dim3(BQ + FF, 2), 256>>>(query, support, qlc, qrc, slc, srrc,
                                            emb, mc);
    // 2) GCN projection with tanh -> nb (4106 x 256); qn = nb rows 0..4095, sn = 4096..
    gemm_gcn<<<dim3(2, (MPAD / 128)), 256>>>(mc, gcnw, gcnwb, gcnb, nb, MROWS);
    // 3) encoders (nb viewed as (BQ,512) / (FF,512))
    encoder_kernel<<<FF, 256>>>(nb + (size_t)2 * BQ * DD, senc, p1w, p1b, p2w, p2b, lng, lnb);
    encoder_kernel<<<BQ, 256>>>(nb, qg, p1w, p1b, p2w, p2b, lng, lnb);
    // 4) support_g mean + normalized copy
    avgnorm_kernel<<<1, 512>>>(sg, sgn, senc);
    // 5) packed sgr + bias
    pack_kernel<<<NG / 8, 256>>>(sgr, biasp, whh, sg, bih, bhh);

    dim3 gg(NG / 128, BQ / 128);
    // 6) Gbase = qg @ Wih_sel^T + (bih+bhh)_packed   (== step-1 gates, h_r = 0)
    gemm_epi<<<gg, 256>>>(qg, wih, KDIM, Gbase, nullptr, biasp);
    // 7) step 1 (c = 0)
    lstm_step_kernel<<<(BQ * DMV) / 256, 256>>>(Gbase, qg, c, h, 1);
    // 8) steps 2..4: gates = h @ Whh_sel[:, :512]^T + Gbase + sgr
    for (int s = 0; s < 3; s++) {
        gemm_epi<<<gg, 256>>>(h, whh, HID, gates, Gbase, sgr);
        lstm_step_kernel<<<(BQ * DMV) / 256, 256>>>(gates, qg, c, h, 0);
    }
    // 9) output cosine
    final_kernel<<<BQ / 8, 256>>>(out, h, sgn);
}

// round 6
// speedup vs baseline: 3.1980x; 3.1980x over previous
#include <cuda_runtime.h>
#include <math.h>

#define VV   200000
#define BQ   2048
#define FF   5
#define NNB  64
#define KSEL 32
#define DD   256
#define DMV  512     // DM
#define HID  1024    // 2*DM
#define NG   2048    // packed gate cols: i,f,g,o each [:512]
#define MROWS (2*(BQ+FF))   // 4106 gcn rows
#define MPAD  4224
#define ER    (BQ + FF)     // 2053 encoder rows
#define ERPAD 2176

// ---------------- static scratch ----------------
__device__ float g_meancat[MPAD*2*DD];        // 4224 x 512
__device__ float g_nb[MPAD*DD];               // 4224 x 256  == 2112 x 512 enc input
__device__ float g_H[ERPAD*2*DMV];            // 2176 x 1024
__device__ float g_O[ERPAD*DMV];              // 2176 x 512
__device__ float g_enc[ERPAD*DMV];            // rows 0..2047 qg, 2048..2052 senc
__device__ float g_sg[DMV];
__device__ float g_sgn[DMV];
__device__ float g_sgr[NG];
__device__ float g_biasp[NG];
__device__ float g_Gbase[(size_t)BQ*NG];
__device__ float g_gates[(size_t)BQ*NG];
__device__ float g_c[BQ*DMV];
__device__ float g_h[BQ*DMV];

// ---------------- helpers ----------------
__device__ __forceinline__ float warp_reduce_sum(float v) {
#pragma unroll
    for (int o = 16; o > 0; o >>= 1) v += __shfl_down_sync(0xffffffffu, v, o);
    return v;
}
__device__ __forceinline__ float sigmoidf_(float x) { return 1.0f / (1.0f + expf(-x)); }
__device__ __forceinline__ int clamp_id(int id) { return (id < 0 || id > VV) ? VV : id; }

__device__ __forceinline__ float block_reduce_256(float v, float* red) {
    int lane = threadIdx.x & 31, w = threadIdx.x >> 5;
    v = warp_reduce_sum(v);
    if (lane == 0) red[w] = v;
    __syncthreads();
    if (threadIdx.x == 0) {
        float s = 0.f;
#pragma unroll
        for (int i = 0; i < 8; i++) s += red[i];
        red[0] = s;
    }
    __syncthreads();
    float s = red[0];
    __syncthreads();
    return s;
}

// ---------------- neighbor encoder: top-K select + mean of (rel,ent) ----------------
__global__ __launch_bounds__(256) void nbenc_kernel(
    const int* __restrict__ query, const int* __restrict__ support,
    const int* __restrict__ qlc, const int* __restrict__ qrc,
    const int* __restrict__ slc, const int* __restrict__ srrc,
    const float* __restrict__ emb, float* __restrict__ meancat_out)
{
    int row = blockIdx.x, side = blockIdx.y;
    const int* conn; int id; int r;
    if (row < BQ) {
        conn = (side == 0 ? qlc : qrc) + row * NNB * 2;
        id   = query[row * 2 + side];
        r    = row * 2 + side;
    } else {
        int f = row - BQ;
        conn = (side == 0 ? slc : srrc) + f * NNB * 2;
        id   = support[f * 2 + side];
        r    = 2 * BQ + f * 2 + side;
    }
    id = clamp_id(id);
    int t = threadIdx.x, lane = t & 31, warp = t >> 5;

    __shared__ float csm[DD];
    __shared__ float sims[NNB];
    __shared__ int   sel[NNB];
    __shared__ float red[8];
    __shared__ float cn_s;

    float cv = emb[(size_t)id * DD + t];
    csm[t] = cv;
    float cs = block_reduce_256(cv * cv, red);
    if (t == 0) cn_s = sqrtf(cs);
    __syncthreads();

#pragma unroll
    for (int i = 0; i < 8; i++) {
        int n = warp * 8 + i;
        int eid = clamp_id(conn[n * 2 + 1]);
        const float* er = emb + (size_t)eid * DD;
        float dot = 0.f, nn2 = 0.f;
#pragma unroll
        for (int d = lane; d < DD; d += 32) {
            float e = er[d];
            dot += e * csm[d];
            nn2 += e * e;
        }
        dot = warp_reduce_sum(dot);
        nn2 = warp_reduce_sum(nn2);
        if (lane == 0) sims[n] = dot / fmaxf(cn_s * sqrtf(nn2), 1e-8f);
    }
    __syncthreads();

    if (t < NNB) {
        float s = sims[t];
        int cnt = 0;
#pragma unroll
        for (int m = 0; m < NNB; m++) {
            float sm = sims[m];
            cnt += (sm > s) || (sm == s && m < t);
        }
        sel[t] = (cnt < KSEL);
    }
    __syncthreads();

    float accR = 0.f, accE = 0.f;
    for (int n = 0; n < NNB; n++) {
        if (!sel[n]) continue;
        int rid = clamp_id(conn[n * 2 + 0]);
        int eid = clamp_id(conn[n * 2 + 1]);
        accR += emb[(size_t)rid * DD + t];
        accE += emb[(size_t)eid * DD + t];
    }
    float* mc = meancat_out + (size_t)r * (2 * DD);
    mc[t]      = accR * (1.0f / KSEL);
    mc[DD + t] = accE * (1.0f / KSEL);
}

// ---------------- generic double-buffered SGEMM ----------------
// C[M x N] = epi(A[M x K] @ W[N x K]^T + ...), 128x128 tile, BK=8
// EPI: 0 = acc (+v1[n]) (+addmat), 1 = tanh(acc + v1[n] + v2[n]), 2 = relu(acc + v1[n])
// GATE: W row mapping wrow = (n0>>9)*HID + (n0&511) for packed gate columns
template<int EPI, bool GATE>
__global__ __launch_bounds__(256, 2) void sgemm(
    const float* __restrict__ A, int lda, int Mtot,
    const float* __restrict__ W, int ldw, int K,
    float* __restrict__ C, int ldc,
    const float* __restrict__ addmat, int ldm,
    const float* __restrict__ v1, const float* __restrict__ v2)
{
    __shared__ float As[2][8][132];
    __shared__ float Bs[2][8][132];
    const int t = threadIdx.x;
    const int tx = t & 15, ty = t >> 4;
    const int m0 = blockIdx.y * 128, n0 = blockIdx.x * 128;
    const int wbase = GATE ? ((n0 >> 9) * HID + (n0 & 511)) : n0;

    // load-thread mapping
    const int lrow = t >> 1;
    const int lk   = (t & 1) * 4;
    int arow = m0 + lrow; if (arow >= Mtot) arow = Mtot - 1;
    const int brow = wbase + lrow;
    const float* Ap = A + (size_t)arow * lda + lk;
    const float* Wp = W + (size_t)brow * ldw + lk;

    float acc[8][8];
#pragma unroll
    for (int i = 0; i < 8; i++)
#pragma unroll
        for (int j = 0; j < 8; j++) acc[i][j] = 0.f;

    // prologue: stage 0
    {
        float4 ra = *(const float4*)(Ap);
        float4 rb = *(const float4*)(Wp);
        As[0][lk+0][lrow] = ra.x; As[0][lk+1][lrow] = ra.y;
        As[0][lk+2][lrow] = ra.z; As[0][lk+3][lrow] = ra.w;
        Bs[0][lk+0][lrow] = rb.x; Bs[0][lk+1][lrow] = rb.y;
        Bs[0][lk+2][lrow] = rb.z; Bs[0][lk+3][lrow] = rb.w;
    }
    __syncthreads();

    int s = 0;
    for (int k0 = 0; k0 < K; k0 += 8) {
        const bool more = (k0 + 8 < K);
        float4 na, nb4;
        if (more) {
            na  = *(const float4*)(Ap + k0 + 8);
            nb4 = *(const float4*)(Wp + k0 + 8);
        }
#pragma unroll
        for (int k = 0; k < 8; k++) {
            float4 a0 = *(const float4*)&As[s][k][ty * 8];
            float4 a1 = *(const float4*)&As[s][k][ty * 8 + 4];
            float4 b0 = *(const float4*)&Bs[s][k][tx * 8];
            float4 b1 = *(const float4*)&Bs[s][k][tx * 8 + 4];
            float av[8] = {a0.x,a0.y,a0.z,a0.w,a1.x,a1.y,a1.z,a1.w};
            float bv[8] = {b0.x,b0.y,b0.z,b0.w,b1.x,b1.y,b1.z,b1.w};
#pragma unroll
            for (int i = 0; i < 8; i++)
#pragma unroll
                for (int j = 0; j < 8; j++) acc[i][j] += av[i] * bv[j];
        }
        if (more) {
            int ns = s ^ 1;
            As[ns][lk+0][lrow] = na.x;  As[ns][lk+1][lrow] = na.y;
            As[ns][lk+2][lrow] = na.z;  As[ns][lk+3][lrow] = na.w;
            Bs[ns][lk+0][lrow] = nb4.x; Bs[ns][lk+1][lrow] = nb4.y;
            Bs[ns][lk+2][lrow] = nb4.z; Bs[ns][lk+3][lrow] = nb4.w;
            __syncthreads();
            s = ns;
        }
    }

    float vcol[8];
#pragma unroll
    for (int j = 0; j < 8; j++) {
        int n = n0 + tx * 8 + j;
        float v = 0.f;
        if (v1) v += v1[n];
        if (EPI == 1 && v2) v += v2[n];
        vcol[j] = v;
    }
#pragma unroll
    for (int i = 0; i < 8; i++) {
        int m = m0 + ty * 8 + i;
        if (m >= Mtot) break;
        float* crow = C + (size_t)m * ldc + n0 + tx * 8;
        if (EPI == 1) {
#pragma unroll
            for (int j = 0; j < 8; j++) crow[j] = tanhf(acc[i][j] + vcol[j]);
        } else if (EPI == 2) {
#pragma unroll
            for (int j = 0; j < 8; j++) crow[j] = fmaxf(acc[i][j] + vcol[j], 0.f);
        } else {
            if (addmat) {
                const float* mrow = addmat + (size_t)m * ldm + n0 + tx * 8;
#pragma unroll
                for (int j = 0; j < 8; j++) crow[j] = acc[i][j] + vcol[j] + mrow[j];
            } else {
#pragma unroll
                for (int j = 0; j < 8; j++) crow[j] = acc[i][j] + vcol[j];
            }
        }
    }
}

// ---------------- LayerNorm over 512 per row ----------------
__global__ __launch_bounds__(256) void ln_kernel(
    const float* __restrict__ O, float* __restrict__ Y,
    const float* __restrict__ lng, const float* __restrict__ lnb)
{
    int row = blockIdx.x, t = threadIdx.x;
    __shared__ float red[8];
    float o0 = O[(size_t)row * DMV + t];
    float o1 = O[(size_t)row * DMV + t + 256];
    float msum = block_reduce_256(o0 + o1, red);
    float m = msum * (1.0f / DMV);
    float d0 = o0 - m, d1 = o1 - m;
    float vsum = block_reduce_256(d0 * d0 + d1 * d1, red);
    float rstd = rsqrtf(vsum * (1.0f / DMV) + 1e-5f);
    Y[(size_t)row * DMV + t]       = d0 * rstd * lng[t]       + lnb[t];
    Y[(size_t)row * DMV + t + 256] = d1 * rstd * lng[t + 256] + lnb[t + 256];
}

// ---------------- mean over F support rows + normalized copy ----------------
__global__ void avgnorm_kernel(float* __restrict__ sg, float* __restrict__ sgn,
                               const float* __restrict__ senc)
{
    int t = threadIdx.x; // 512 threads
    __shared__ float red[16];
    float s = 0.f;
#pragma unroll
    for (int f = 0; f < FF; f++) s += senc[f * DMV + t];
    s *= (1.0f / FF);
    sg[t] = s;
    int lane = t & 31, w = t >> 5;
    float v = warp_reduce_sum(s * s);
    if (lane == 0) red[w] = v;
    __syncthreads();
    if (t == 0) {
        float tot = 0.f;
#pragma unroll
        for (int i = 0; i < 16; i++) tot += red[i];
        red[0] = sqrtf(tot);
    }
    __syncthreads();
    float nrm = red[0];
    sgn[t] = s / fmaxf(nrm, 1e-12f);
}

// ---------------- packed constants: sgr[n], biasp[n] ----------------
__global__ __launch_bounds__(256) void pack_kernel(
    float* __restrict__ sgr, float* __restrict__ biasp,
    const float* __restrict__ whh, const float* __restrict__ sg,
    const float* __restrict__ bih, const float* __restrict__ bhh)
{
    int n = (blockIdx.x * blockDim.x + threadIdx.x) >> 5;
    int lane = threadIdx.x & 31;
    if (n >= NG) return;
    int jf = (n >> 9) * HID + (n & 511);
    const float* wr = whh + (size_t)jf * HID + DMV;
    float a = 0.f;
#pragma unroll
    for (int k = lane; k < DMV; k += 32) a += wr[k] * sg[k];
    a = warp_reduce_sum(a);
    if (lane == 0) {
        sgr[n] = a;
        biasp[n] = bih[jf] + bhh[jf];
    }
}

// ---------------- LSTM elementwise step ----------------
__global__ __launch_bounds__(256) void lstm_step_kernel(
    const float* __restrict__ G, const float* __restrict__ qg,
    float* __restrict__ c, float* __restrict__ h, int first)
{
    int idx = blockIdx.x * blockDim.x + threadIdx.x;
    int b = idx >> 9, j = idx & 511;
    const float* g = G + (size_t)b * NG;
    float gi = g[j], gf = g[512 + j], gg = g[1024 + j], go = g[1536 + j];
    float cn = sigmoidf_(gi) * tanhf(gg);
    if (!first) cn += sigmoidf_(gf) * c[idx];
    c[idx] = cn;
    h[idx] = qg[idx] + sigmoidf_(go) * tanhf(cn);
}

// ---------------- final cosine output ----------------
__global__ __launch_bounds__(256) void final_kernel(
    float* __restrict__ out, const float* __restrict__ h,
    const float* __restrict__ sgn)
{
    int b = (blockIdx.x * blockDim.x + threadIdx.x) >> 5;
    int lane = threadIdx.x & 31;
    if (b >= BQ) return;
    float nn = 0.f, dd = 0.f;
#pragma unroll
    for (int d = lane; d < DMV; d += 32) {
        float hv = h[(size_t)b * DMV + d];
        nn += hv * hv;
        dd += hv * sgn[d];
    }
    nn = warp_reduce_sum(nn);
    dd = warp_reduce_sum(dd);
    if (lane == 0) out[b] = dd / fmaxf(sqrtf(nn), 1e-12f);
}

// ---------------- input binding ----------------
enum {
    R_query=0, R_support, R_qlc, R_qld, R_qrc, R_qrd, R_slc, R_sld, R_src, R_srd,
    R_emb, R_gcnw, R_gcnwb, R_gcnb, R_p1w, R_p1b, R_p2w, R_p2b, R_lng, R_lnb,
    R_wih, R_whh, R_bih, R_bhh, R_COUNT
};
static const int DICT_SIZES[R_COUNT] = {
    4096, 10, 262144, 2048, 262144, 2048, 640, 5, 640, 5,
    51200256, 131072, 256, 256, 524288, 1024, 524288, 512, 512, 512,
    2097152, 4194304, 4096, 4096
};
static bool sizes_match(const int* s, const int* exp, int n) {
    for (int i = 0; i < n; i++) if (s[i] != exp[i]) return false;
    return true;
}

// ---------------- launcher ----------------
extern "C" void kernel_launch(void* const* d_in, const int* in_sizes, int n_in,
                              void* d_out, int out_size)
{
    int map[R_COUNT];
    if (n_in >= R_COUNT && sizes_match(in_sizes, DICT_SIZES, R_COUNT)) {
        for (int r = 0; r < R_COUNT; r++) map[r] = r;
    } else {
        bool used[64] = {false};
        for (int r = 0; r < R_COUNT; r++) {
            map[r] = 0;
            for (int i = 0; i < n_in && i < 64; i++) {
                if (!used[i] && in_sizes[i] == DICT_SIZES[r]) { map[r] = i; used[i] = true; break; }
            }
        }
    }

    const int*   query   = (const int*)d_in[map[R_query]];
    const int*   support = (const int*)d_in[map[R_support]];
    const int*   qlc     = (const int*)d_in[map[R_qlc]];
    const int*   qrc     = (const int*)d_in[map[R_qrc]];
    const int*   slc     = (const int*)d_in[map[R_slc]];
    const int*   srrc    = (const int*)d_in[map[R_src]];
    const float* emb     = (const float*)d_in[map[R_emb]];
    const float* gcnw    = (const float*)d_in[map[R_gcnw]];
    const float* gcnwb   = (const float*)d_in[map[R_gcnwb]];
    const float* gcnb    = (const float*)d_in[map[R_gcnb]];
    const float* p1w     = (const float*)d_in[map[R_p1w]];
    const float* p1b     = (const float*)d_in[map[R_p1b]];
    const float* p2w     = (const float*)d_in[map[R_p2w]];
    const float* p2b     = (const float*)d_in[map[R_p2b]];
    const float* lng     = (const float*)d_in[map[R_lng]];
    const float* lnb     = (const float*)d_in[map[R_lnb]];
    const float* wih     = (const float*)d_in[map[R_wih]];
    const float* whh     = (const float*)d_in[map[R_whh]];
    const float* bih     = (const float*)d_in[map[R_bih]];
    const float* bhh     = (const float*)d_in[map[R_bhh]];
    float* out = (float*)d_out;

    float *mc, *nb, *H, *O, *enc, *sg, *sgn, *sgr, *biasp, *Gbase, *gates, *c, *h;
    cudaGetSymbolAddress((void**)&mc,    g_meancat);
    cudaGetSymbolAddress((void**)&nb,    g_nb);
    cudaGetSymbolAddress((void**)&H,     g_H);
    cudaGetSymbolAddress((void**)&O,     g_O);
    cudaGetSymbolAddress((void**)&enc,   g_enc);
    cudaGetSymbolAddress((void**)&sg,    g_sg);
    cudaGetSymbolAddress((void**)&sgn,   g_sgn);
    cudaGetSymbolAddress((void**)&sgr,   g_sgr);
    cudaGetSymbolAddress((void**)&biasp, g_biasp);
    cudaGetSymbolAddress((void**)&Gbase, g_Gbase);
    cudaGetSymbolAddress((void**)&gates, g_gates);
    cudaGetSymbolAddress((void**)&c,     g_c);
    cudaGetSymbolAddress((void**)&h,     g_h);

    float* qg   = enc;                       // rows 0..2047
    float* senc = enc + (size_t)BQ * DMV;    // rows 2048..2052

    // 1) neighbor top-K means -> meancat (4106 x 512)
    nbenc_kernel<<<dim3(BQ + FF, 2), 256>>>(query, support, qlc, qrc, slc, srrc, emb, mc);
    // 2) GCN: nb = tanh(mc @ gcnw^T + wb + b)   (4106 x 256; viewed as 2053 x 512)
    sgemm<1,false><<<dim3(2, MPAD/128), 256>>>(mc, 2*DD, MROWS, gcnw, 2*DD, 2*DD,
                                               nb, DD, nullptr, 0, gcnwb, gcnb);
    // 3) encoder as batched GEMMs over all 2053 rows
    //    H = relu(X @ p1w^T + p1b)
    sgemm<2,false><<<dim3(8, ERPAD/128), 256>>>(nb, DMV, ER, p1w, DMV, DMV,
                                                H, 2*DMV, nullptr, 0, p1b, nullptr);
    //    O = H @ p2w^T + p2b + X
    sgemm<0,false><<<dim3(4, ERPAD/128), 256>>>(H, 2*DMV, ER, p2w, 2*DMV, 2*DMV,
                                                O, DMV, nb, DMV, p2b, nullptr);
    //    LayerNorm -> enc (qg | senc)
    ln_kernel<<<ER, 256>>>(O, enc, lng, lnb);
    // 4) support_g mean + normalized copy
    avgnorm_kernel<<<1, 512>>>(sg, sgn, senc);
    // 5) packed sgr + bias
    pack_kernel<<<NG / 8, 256>>>(sgr, biasp, whh, sg, bih, bhh);

    dim3 gg(NG / 128, BQ / 128);
    // 6) Gbase = qg @ Wih_sel^T + (bih+bhh)_packed  (== step-1 gates)
    sgemm<0,true><<<gg, 256>>>(qg, DMV, BQ, wih, DMV, DMV,
                               Gbase, NG, nullptr, 0, biasp, nullptr);
    // 7) step 1 (c = 0)
    lstm_step_kernel<<<(BQ * DMV) / 256, 256>>>(Gbase, qg, c, h, 1);
    // 8) steps 2..4: gates = h @ Whh_sel[:, :512]^T + Gbase + sgr
    for (int s = 0; s < 3; s++) {
        sgemm<0,true><<<gg, 256>>>(h, DMV, BQ, whh, HID, DMV,
                                   gates, NG, Gbase, NG, sgr, nullptr);
        lstm_step_kernel<<<(BQ * DMV) / 256, 256>>>(gates, qg, c, h, 0);
    }
    // 9) output cosine
    final_kernel<<<BQ / 8, 256>>>(out, h, sgn);
}